// round 15
// baseline (speedup 1.0000x reference)
#include <cuda_runtime.h>
#include <cuda_bf16.h>
#include <math_constants.h>
#include <cstdint>

// Problem constants
#define BATCH 4
#define SEQ   2048
#define EMBD  1024
#define NHEAD 16
#define HDIM  64
#define QKV3  (3 * EMBD)
#define MTOK  (BATCH * SEQ)   // 8192
#define KD8   (EMBD / 8)      // 128 k-tiles of 8

// ---------------------------------------------------------------------------
// Scratch (__device__ globals)
// A-frag layout [M/16][K/8][lane 32][slot 4] floats
// B-frag layout [N/8][K/8][lane 32][slot 2] floats
// V: token-pair-packed bf16 big/small, word = pack(V[2t][d], V[2t+1][d])
// ---------------------------------------------------------------------------
__device__ __align__(16) float    g_xf [(size_t)MTOK * EMBD];     // x (tf32)
__device__ __align__(16) float    g_wfa[(size_t)EMBD * QKV3];     // w_attn^T
__device__ __align__(16) float    g_wfp[(size_t)EMBD * EMBD];     // w_proj^T
__device__ __align__(16) float    g_af [(size_t)MTOK * EMBD];     // attn out
__device__ __align__(16) float    g_q  [(size_t)MTOK * EMBD];     // Q fp32
__device__ __align__(16) uint32_t g_kb [(size_t)MTOK * EMBD / 2]; // K bf16 big
__device__ __align__(16) uint32_t g_ks [(size_t)MTOK * EMBD / 2]; // K bf16 small
__device__ __align__(16) uint32_t g_vbb[(size_t)(MTOK / 2) * EMBD]; // V big pairs
__device__ __align__(16) uint32_t g_vbs[(size_t)(MTOK / 2) * EMBD]; // V small pairs

// ---------------------------------------------------------------------------
// Helpers
// ---------------------------------------------------------------------------
__device__ __forceinline__ float f2tf(float x) {
    uint32_t u;
    asm("cvt.rna.tf32.f32 %0, %1;" : "=r"(u) : "f"(x));
    return __uint_as_float(u);
}
__device__ __forceinline__ float bfr(float x) {
    return __bfloat162float(__float2bfloat16_rn(x));
}
__device__ __forceinline__ uint32_t pack_bf(float lo, float hi) {
    __nv_bfloat162 h = __floats2bfloat162_rn(lo, hi);
    return *reinterpret_cast<uint32_t*>(&h);
}
__device__ __forceinline__ void split2(float2 v, uint32_t& bp, uint32_t& sp) {
    float bx = bfr(v.x), by = bfr(v.y);
    bp = pack_bf(bx, by);
    sp = pack_bf(v.x - bx, v.y - by);
}

__device__ __forceinline__ void mma_tf32(float c[4], const uint32_t a[4],
                                         const uint32_t b[2]) {
    asm volatile(
        "mma.sync.aligned.m16n8k8.row.col.f32.tf32.tf32.f32 "
        "{%0,%1,%2,%3}, {%4,%5,%6,%7}, {%8,%9}, {%0,%1,%2,%3};"
        : "+f"(c[0]), "+f"(c[1]), "+f"(c[2]), "+f"(c[3])
        : "r"(a[0]), "r"(a[1]), "r"(a[2]), "r"(a[3]), "r"(b[0]), "r"(b[1]));
}
__device__ __forceinline__ void mma_bf16(float c[4], const uint32_t a[4],
                                         const uint32_t b[2]) {
    asm volatile(
        "mma.sync.aligned.m16n8k16.row.col.f32.bf16.bf16.f32 "
        "{%0,%1,%2,%3}, {%4,%5,%6,%7}, {%8,%9}, {%0,%1,%2,%3};"
        : "+f"(c[0]), "+f"(c[1]), "+f"(c[2]), "+f"(c[3])
        : "r"(a[0]), "r"(a[1]), "r"(a[2]), "r"(a[3]), "r"(b[0]), "r"(b[1]));
}

__device__ __forceinline__ void cp_async16p(void* dst_smem, const void* src) {
    uint32_t sa = (uint32_t)__cvta_generic_to_shared(dst_smem);
    asm volatile("cp.async.cg.shared.global [%0], [%1], 16;\n"
                 :: "r"(sa), "l"(src));
}
__device__ __forceinline__ void cp_commit() {
    asm volatile("cp.async.commit_group;\n");
}
template<int N>
__device__ __forceinline__ void cp_wait() {
    asm volatile("cp.async.wait_group %0;\n" :: "n"(N));
}

// ---------------------------------------------------------------------------
// Prep kernels (destinations referenced in DEVICE code only)
// ---------------------------------------------------------------------------
__global__ __launch_bounds__(256) void prep_a_kernel(
    const float* __restrict__ src)
{
    size_t id = (size_t)blockIdx.x * 256 + threadIdx.x;
    size_t tile = id >> 5;
    int lane = (int)(id & 31);
    int mt = (int)(tile >> 7), kt = (int)(tile & 127);
    int g = lane >> 2, tg = lane & 3;
    const float* s = src + (size_t)(mt * 16 + g) * EMBD + kt * 8 + tg;
    float v0 = s[0];
    float v1 = s[8 * EMBD];
    float v2 = s[4];
    float v3 = s[8 * EMBD + 4];
    *reinterpret_cast<float4*>(g_xf + id * 4) =
        make_float4(f2tf(v0), f2tf(v1), f2tf(v2), f2tf(v3));
}

__device__ __forceinline__ void prep_b_body(
    const float* __restrict__ w, float* __restrict__ dst, int N)
{
    size_t id = (size_t)blockIdx.x * 256 + threadIdx.x;
    size_t tile = id >> 5;
    int lane = (int)(id & 31);
    int nt = (int)(tile >> 7), kt = (int)(tile & 127);
    int g = lane >> 2, tg = lane & 3;
    int n = nt * 8 + g, k = kt * 8 + tg;
    float v0 = w[(size_t)k * N + n];
    float v1 = w[(size_t)(k + 4) * N + n];
    *reinterpret_cast<float2*>(dst + id * 2) = make_float2(f2tf(v0), f2tf(v1));
}

__global__ __launch_bounds__(256) void prep_b_attn_kernel(
    const float* __restrict__ w)
{
    prep_b_body(w, g_wfa, QKV3);
}

__global__ __launch_bounds__(256) void prep_b_proj_kernel(
    const float* __restrict__ w)
{
    prep_b_body(w, g_wfp, EMBD);
}

// ---------------------------------------------------------------------------
// TF32 GEMM, fragment-major operands, BK=32, 3-stage cp.async pipeline.
// mode 0: out[row][col] (proj).  mode 1: qkv epilogue (Q / K-split / V-pairs).
// ---------------------------------------------------------------------------
#define STG_A 4096
#define STG_B 4096
#define STG_FLOATS (STG_A + STG_B)
#define GEMM_SMEM_BYTES (3 * STG_FLOATS * 4)   // 98304

__device__ __forceinline__ void gemm_body(
    const float* __restrict__ Af, const float* __restrict__ Bf,
    const float* __restrict__ bias, float* __restrict__ C, int mode)
{
    extern __shared__ float gsm[];

    const int tid = threadIdx.x, wid = tid >> 5, lane = tid & 31;
    const int g = lane >> 2, tg = lane & 3;
    const int wm = wid & 3, wn = wid >> 2;
    const int row0 = blockIdx.y * 128, col0 = blockIdx.x * 128;
    const int mt0 = blockIdx.y * 8, nt0 = blockIdx.x * 16;

    float c[2][8][4];
#pragma unroll
    for (int mf = 0; mf < 2; mf++)
#pragma unroll
        for (int nf = 0; nf < 8; nf++)
#pragma unroll
            for (int i = 0; i < 4; i++) c[mf][nf][i] = 0.f;

    auto fill = [&](int kb, int st) {
        float* as = gsm + st * STG_FLOATS;
        float* bs = as + STG_A;
#pragma unroll
        for (int l = 0; l < 4; l++) {
            int ch = tid + l * 256;
            int mtl = ch >> 7, off = (ch & 127) * 4;
            cp_async16p(&as[mtl * 512 + off],
                        &Af[((size_t)(mt0 + mtl) * KD8 + kb * 4) * 128 + off]);
        }
#pragma unroll
        for (int l = 0; l < 4; l++) {
            int ch = tid + l * 256;
            int ntl = ch >> 6, off = (ch & 63) * 4;
            cp_async16p(&bs[ntl * 256 + off],
                        &Bf[((size_t)(nt0 + ntl) * KD8 + kb * 4) * 64 + off]);
        }
        cp_commit();
    };

    const int nk = 32;   // K=1024 / BK=32
    fill(0, 0);
    fill(1, 1);

    for (int it = 0; it < nk; it++) {
        if (it + 1 < nk) cp_wait<1>(); else cp_wait<0>();
        __syncthreads();

        const float* as = gsm + (it % 3) * STG_FLOATS;
        const float* bs = as + STG_A;

#pragma unroll
        for (int ktl = 0; ktl < 4; ktl++) {
            uint32_t a[2][4], b[8][2];
#pragma unroll
            for (int mf = 0; mf < 2; mf++) {
                float4 av = *reinterpret_cast<const float4*>(
                    &as[((wm * 2 + mf) * 4 + ktl) * 128 + lane * 4]);
                a[mf][0] = __float_as_uint(av.x);
                a[mf][1] = __float_as_uint(av.y);
                a[mf][2] = __float_as_uint(av.z);
                a[mf][3] = __float_as_uint(av.w);
            }
#pragma unroll
            for (int nf = 0; nf < 8; nf++) {
                float2 bv = *reinterpret_cast<const float2*>(
                    &bs[((wn * 8 + nf) * 4 + ktl) * 64 + lane * 2]);
                b[nf][0] = __float_as_uint(bv.x);
                b[nf][1] = __float_as_uint(bv.y);
            }
#pragma unroll
            for (int mf = 0; mf < 2; mf++)
#pragma unroll
                for (int nf = 0; nf < 8; nf++)
                    mma_tf32(c[mf][nf], a[mf], b[nf]);
        }

        if (it + 2 < nk) fill(it + 2, (it + 2) % 3);
    }

    const int region = col0 >> 10;   // mode 1: 0=Q, 1=K, 2=V

#pragma unroll
    for (int mf = 0; mf < 2; mf++) {
        int r_lo = row0 + wm * 32 + mf * 16 + g;
#pragma unroll
        for (int nf = 0; nf < 8; nf++) {
            int cc = col0 + wn * 64 + nf * 8 + tg * 2;
            float b0 = bias[cc], b1 = bias[cc + 1];
            float v00 = c[mf][nf][0] + b0, v01 = c[mf][nf][1] + b1;
            float v10 = c[mf][nf][2] + b0, v11 = c[mf][nf][3] + b1;
            if (mode == 0) {
                *reinterpret_cast<float2*>(&C[(size_t)r_lo * EMBD + cc]) =
                    make_float2(v00, v01);
                *reinterpret_cast<float2*>(&C[(size_t)(r_lo + 8) * EMBD + cc]) =
                    make_float2(v10, v11);
            } else if (region == 0) {
                *reinterpret_cast<float2*>(&g_q[(size_t)r_lo * EMBD + cc]) =
                    make_float2(v00, v01);
                *reinterpret_cast<float2*>(&g_q[(size_t)(r_lo + 8) * EMBD + cc]) =
                    make_float2(v10, v11);
            } else if (region == 1) {
                int col = cc - EMBD;
                float h00 = bfr(v00), h01 = bfr(v01);
                float h10 = bfr(v10), h11 = bfr(v11);
                size_t w0 = ((size_t)r_lo * EMBD + col) >> 1;
                size_t w1 = ((size_t)(r_lo + 8) * EMBD + col) >> 1;
                g_kb[w0] = pack_bf(h00, h01);
                g_ks[w0] = pack_bf(v00 - h00, v01 - h01);
                g_kb[w1] = pack_bf(h10, h11);
                g_ks[w1] = pack_bf(v10 - h10, v11 - h11);
            } else {
                // V: token-pair-packed bf16 big/small. Rows r_lo and r_lo^1
                // live in lanes g and g^1 -> exchange via shfl_xor(4).
                int col = cc - 2 * EMBD;
                float p00 = __shfl_xor_sync(0xffffffffu, v00, 4);
                float p01 = __shfl_xor_sync(0xffffffffu, v01, 4);
                float p10 = __shfl_xor_sync(0xffffffffu, v10, 4);
                float p11 = __shfl_xor_sync(0xffffffffu, v11, 4);
                if ((g & 1) == 0) {   // even row: owns pair (r_lo, r_lo+1)
                    size_t tp0 = (size_t)(r_lo >> 1) * EMBD + col;
                    size_t tp1 = (size_t)((r_lo + 8) >> 1) * EMBD + col;
                    uint32_t b00, s00, b01, s01, b10, s10, b11, s11;
                    split2(make_float2(v00, p00), b00, s00);
                    split2(make_float2(v01, p01), b01, s01);
                    split2(make_float2(v10, p10), b10, s10);
                    split2(make_float2(v11, p11), b11, s11);
                    *reinterpret_cast<uint2*>(&g_vbb[tp0]) = make_uint2(b00, b01);
                    *reinterpret_cast<uint2*>(&g_vbs[tp0]) = make_uint2(s00, s01);
                    *reinterpret_cast<uint2*>(&g_vbb[tp1]) = make_uint2(b10, b11);
                    *reinterpret_cast<uint2*>(&g_vbs[tp1]) = make_uint2(s10, s11);
                }
            }
        }
    }
}

__global__ __launch_bounds__(256, 2) void qkv_gemm_kernel(
    const float* __restrict__ bias)
{
    gemm_body(g_xf, g_wfa, bias, nullptr, 1);
}

__global__ __launch_bounds__(256, 2) void proj_gemm_kernel(
    const float* __restrict__ bias, float* __restrict__ out)
{
    gemm_body(g_af, g_wfp, bias, out, 0);
}

// ---------------------------------------------------------------------------
// Tensor-core flash attention (causal), 64-row q-blocks, 4 warps (round-9
// shape). PV now uses DIRECT register P fragments (bf16 split) — the bf16
// m16n8k16 A-fragment equals the S C-fragment, so the P smem round-trip,
// f2tf, and syncwarp are gone. V is bf16 big/small (token-pair packed).
// qt reversed: heavy diagonal blocks first.
// ---------------------------------------------------------------------------
#define QKW 36
#define VW  72
#define QBW (64 * QKW)                      // 2304 words per Q bf16 buffer
#define STAGE_W (2 * 64 * QKW + 2 * 32 * VW)  // kb+ks+vbb+vbs = 9216 words
#define OFF_ST0 (2 * QBW)                   // 4608
#define ATT_SMEM_BYTES ((OFF_ST0 + 2 * STAGE_W) * 4)   // 92160

__device__ __forceinline__ void st_afrag(float v, int r, int c) {
    size_t idx = ((size_t)(r >> 4) * KD8 + (c >> 3)) * 128
               + ((r & 7) * 4 + (c & 3)) * 4
               + ((r >> 3) & 1) + 2 * ((c >> 2) & 1);
    g_af[idx] = f2tf(v);
}

__global__ __launch_bounds__(128) void flash_attn_kernel()
{
    extern __shared__ uint32_t smw[];
    uint32_t* qb = smw;
    uint32_t* qs = smw + QBW;

    const int tid = threadIdx.x, lane = tid & 31, w = tid >> 5;
    const int g = lane >> 2, tg = lane & 3;
    const int qt = (SEQ / 64) - 1 - blockIdx.x;   // heavy blocks first
    const int h = blockIdx.y, b = blockIdx.z;

    const int bsq = b * SEQ;
    const float scale = 0.125f;

    auto issue_kv = [&](int kt, int st) {
        uint32_t* kbs = smw + OFF_ST0 + st * STAGE_W;
        uint32_t* kss = kbs + 64 * QKW;
        uint32_t* vbb = kss + 64 * QKW;
        uint32_t* vbs = vbb + 32 * VW;
        const size_t tok0 = (size_t)(bsq + kt * 64);
        const size_t tp0 = tok0 >> 1;
#pragma unroll
        for (int l = 0; l < 4; l++) {           // kb: 512 chunks
            int id = tid + l * 128;
            int r = id >> 3, ch = id & 7;
            cp_async16p(&kbs[r * QKW + ch * 4],
                        &g_kb[(tok0 + r) * 512 + h * 32 + ch * 4]);
        }
#pragma unroll
        for (int l = 0; l < 4; l++) {           // ks
            int id = tid + l * 128;
            int r = id >> 3, ch = id & 7;
            cp_async16p(&kss[r * QKW + ch * 4],
                        &g_ks[(tok0 + r) * 512 + h * 32 + ch * 4]);
        }
#pragma unroll
        for (int l = 0; l < 4; l++) {           // vbb: 512 chunks (32 rows x 16)
            int id = tid + l * 128;
            int r = id >> 4, ch = id & 15;
            cp_async16p(&vbb[r * VW + ch * 4],
                        &g_vbb[(tp0 + r) * EMBD + h * HDIM + ch * 4]);
        }
#pragma unroll
        for (int l = 0; l < 4; l++) {           // vbs
            int id = tid + l * 128;
            int r = id >> 4, ch = id & 15;
            cp_async16p(&vbs[r * VW + ch * 4],
                        &g_vbs[(tp0 + r) * EMBD + h * HDIM + ch * 4]);
        }
        cp_commit();
    };

    issue_kv(0, 0);

    // Q tile (scaled, bf16 big/small) into smem — 64 rows x 16 chunks
#pragma unroll
    for (int l = 0; l < 8; l++) {
        int id = tid + l * 128;
        int r = id >> 4, c = (id & 15) * 4;
        float4 v = *reinterpret_cast<const float4*>(
            &g_q[(size_t)(bsq + qt * 64 + r) * EMBD + h * HDIM + c]);
        v.x *= scale; v.y *= scale; v.z *= scale; v.w *= scale;
        float bx = bfr(v.x), by = bfr(v.y), bz = bfr(v.z), bw = bfr(v.w);
        *reinterpret_cast<uint2*>(&qb[r * QKW + (c >> 1)]) =
            make_uint2(pack_bf(bx, by), pack_bf(bz, bw));
        *reinterpret_cast<uint2*>(&qs[r * QKW + (c >> 1)]) =
            make_uint2(pack_bf(v.x - bx, v.y - by), pack_bf(v.z - bz, v.w - bw));
    }

    float m0 = -CUDART_INF_F, m1 = -CUDART_INF_F;
    float l0 = 0.f, l1 = 0.f;
    float o[8][4];
#pragma unroll
    for (int nf = 0; nf < 8; nf++)
#pragma unroll
        for (int i = 0; i < 4; i++) o[nf][i] = 0.f;

    const int row_g = qt * 64 + w * 16 + g;
    const int nkt = qt + 1;

    for (int kt = 0; kt < nkt; kt++) {
        if (kt + 1 < nkt) { issue_kv(kt + 1, (kt + 1) & 1); cp_wait<1>(); }
        else cp_wait<0>();
        __syncthreads();

        const int st = kt & 1;
        const uint32_t* kbs = smw + OFF_ST0 + st * STAGE_W;
        const uint32_t* kss = kbs + 64 * QKW;
        const uint32_t* vbb = kss + 64 * QKW;
        const uint32_t* vbs = vbb + 32 * VW;

        // S = Q K^T (bf16x3, m16n8k16)
        float s[8][4];
#pragma unroll
        for (int nf = 0; nf < 8; nf++)
#pragma unroll
            for (int i = 0; i < 4; i++) s[nf][i] = 0.f;

#pragma unroll
        for (int kc = 0; kc < 4; kc++) {
            const int d0w = kc * 8;
            const int r0 = w * 16 + g;
            uint32_t ab[4], as2[4];
            ab[0] = qb[r0 * QKW + d0w + tg];
            ab[1] = qb[(r0 + 8) * QKW + d0w + tg];
            ab[2] = qb[r0 * QKW + d0w + tg + 4];
            ab[3] = qb[(r0 + 8) * QKW + d0w + tg + 4];
            as2[0] = qs[r0 * QKW + d0w + tg];
            as2[1] = qs[(r0 + 8) * QKW + d0w + tg];
            as2[2] = qs[r0 * QKW + d0w + tg + 4];
            as2[3] = qs[(r0 + 8) * QKW + d0w + tg + 4];
#pragma unroll
            for (int nf = 0; nf < 8; nf++) {
                const int t0 = nf * 8;
                uint32_t bb[2], bs[2];
                bb[0] = kbs[(t0 + g) * QKW + d0w + tg];
                bb[1] = kbs[(t0 + g) * QKW + d0w + tg + 4];
                bs[0] = kss[(t0 + g) * QKW + d0w + tg];
                bs[1] = kss[(t0 + g) * QKW + d0w + tg + 4];
                mma_bf16(s[nf], ab, bb);
                mma_bf16(s[nf], as2, bb);
                mma_bf16(s[nf], ab, bs);
            }
        }

        // Causal mask (diagonal tile only)
        if (kt == qt) {
#pragma unroll
            for (int nf = 0; nf < 8; nf++) {
                int cbase = kt * 64 + nf * 8 + 2 * tg;
                if (cbase > row_g)         s[nf][0] = -CUDART_INF_F;
                if (cbase + 1 > row_g)     s[nf][1] = -CUDART_INF_F;
                if (cbase > row_g + 8)     s[nf][2] = -CUDART_INF_F;
                if (cbase + 1 > row_g + 8) s[nf][3] = -CUDART_INF_F;
            }
        }

        // Online softmax (P overwrites s in registers; no smem round-trip)
        float t0m = -CUDART_INF_F, t1m = -CUDART_INF_F;
#pragma unroll
        for (int nf = 0; nf < 8; nf++) {
            t0m = fmaxf(t0m, fmaxf(s[nf][0], s[nf][1]));
            t1m = fmaxf(t1m, fmaxf(s[nf][2], s[nf][3]));
        }
        t0m = fmaxf(t0m, __shfl_xor_sync(0xffffffffu, t0m, 1));
        t0m = fmaxf(t0m, __shfl_xor_sync(0xffffffffu, t0m, 2));
        t1m = fmaxf(t1m, __shfl_xor_sync(0xffffffffu, t1m, 1));
        t1m = fmaxf(t1m, __shfl_xor_sync(0xffffffffu, t1m, 2));

        float mn0 = fmaxf(m0, t0m), mn1 = fmaxf(m1, t1m);
        float c0 = __expf(m0 - mn0), c1 = __expf(m1 - mn1);

        float psum0 = 0.f, psum1 = 0.f;
#pragma unroll
        for (int nf = 0; nf < 8; nf++) {
            s[nf][0] = __expf(s[nf][0] - mn0);
            s[nf][1] = __expf(s[nf][1] - mn0);
            s[nf][2] = __expf(s[nf][2] - mn1);
            s[nf][3] = __expf(s[nf][3] - mn1);
            psum0 += s[nf][0] + s[nf][1];
            psum1 += s[nf][2] + s[nf][3];
        }
        psum0 += __shfl_xor_sync(0xffffffffu, psum0, 1);
        psum0 += __shfl_xor_sync(0xffffffffu, psum0, 2);
        psum1 += __shfl_xor_sync(0xffffffffu, psum1, 1);
        psum1 += __shfl_xor_sync(0xffffffffu, psum1, 2);

        l0 = l0 * c0 + psum0;
        l1 = l1 * c1 + psum1;
        m0 = mn0; m1 = mn1;

#pragma unroll
        for (int nf = 0; nf < 8; nf++) {
            o[nf][0] *= c0; o[nf][1] *= c0;
            o[nf][2] *= c1; o[nf][3] *= c1;
        }

        // O += P V (bf16, m16n8k16): P A-fragments packed straight from s.
#pragma unroll
        for (int kc = 0; kc < 4; kc++) {
            uint32_t pb[4], psm[4];
            split2(make_float2(s[2 * kc][0],     s[2 * kc][1]),     pb[0], psm[0]);
            split2(make_float2(s[2 * kc][2],     s[2 * kc][3]),     pb[1], psm[1]);
            split2(make_float2(s[2 * kc + 1][0], s[2 * kc + 1][1]), pb[2], psm[2]);
            split2(make_float2(s[2 * kc + 1][2], s[2 * kc + 1][3]), pb[3], psm[3]);
#pragma unroll
            for (int nf = 0; nf < 8; nf++) {
                const int d0 = nf * 8;
                uint32_t bvb[2], bvs[2];
                bvb[0] = vbb[(8 * kc + tg) * VW + d0 + g];
                bvb[1] = vbb[(8 * kc + tg + 4) * VW + d0 + g];
                bvs[0] = vbs[(8 * kc + tg) * VW + d0 + g];
                bvs[1] = vbs[(8 * kc + tg + 4) * VW + d0 + g];
                mma_bf16(o[nf], pb, bvb);
                mma_bf16(o[nf], psm, bvb);
                mma_bf16(o[nf], pb, bvs);
            }
        }
        __syncthreads();   // stage reuse protection
    }

    // Epilogue: normalize + write proj A-operand in fragment layout
    float inv0 = 1.f / l0, inv1 = 1.f / l1;
    const int gr0 = bsq + row_g;
#pragma unroll
    for (int nf = 0; nf < 8; nf++) {
        int c0c = h * HDIM + nf * 8 + 2 * tg;
        st_afrag(o[nf][0] * inv0, gr0,     c0c);
        st_afrag(o[nf][1] * inv0, gr0,     c0c + 1);
        st_afrag(o[nf][2] * inv1, gr0 + 8, c0c);
        st_afrag(o[nf][3] * inv1, gr0 + 8, c0c + 1);
    }
}

// ---------------------------------------------------------------------------
// Launch
// ---------------------------------------------------------------------------
extern "C" void kernel_launch(void* const* d_in, const int* in_sizes, int n_in,
                              void* d_out, int out_size)
{
    const float* x      = (const float*)d_in[0];
    const float* w_attn = (const float*)d_in[1];
    const float* b_attn = (const float*)d_in[2];
    const float* w_proj = (const float*)d_in[3];
    const float* b_proj = (const float*)d_in[4];
    float* out = (float*)d_out;

    cudaFuncSetAttribute(qkv_gemm_kernel,
                         cudaFuncAttributeMaxDynamicSharedMemorySize,
                         GEMM_SMEM_BYTES);
    cudaFuncSetAttribute(proj_gemm_kernel,
                         cudaFuncAttributeMaxDynamicSharedMemorySize,
                         GEMM_SMEM_BYTES);
    cudaFuncSetAttribute(flash_attn_kernel,
                         cudaFuncAttributeMaxDynamicSharedMemorySize,
                         ATT_SMEM_BYTES);

    // Prep: x -> A-frag, W^T -> B-frag (tf32-rounded once)
    prep_a_kernel<<<(unsigned)(((size_t)(MTOK / 16) * KD8 * 32) / 256), 256>>>(x);
    prep_b_attn_kernel<<<(unsigned)(((size_t)(QKV3 / 8) * KD8 * 32) / 256), 256>>>(
        w_attn);
    prep_b_proj_kernel<<<(unsigned)(((size_t)(EMBD / 8) * KD8 * 32) / 256), 256>>>(
        w_proj);

    // QKV GEMM -> Q / K-split / V-pair buffers
    qkv_gemm_kernel<<<dim3(QKV3 / 128, MTOK / 128), 256, GEMM_SMEM_BYTES>>>(
        b_attn);

    // Flash attention -> proj A-operand (frag layout)
    flash_attn_kernel<<<dim3(SEQ / 64, NHEAD, BATCH), 128, ATT_SMEM_BYTES>>>();

    // Proj GEMM -> out
    proj_gemm_kernel<<<dim3(EMBD / 128, MTOK / 128), 256, GEMM_SMEM_BYTES>>>(
        b_proj, out);
}

// round 16
// speedup vs baseline: 1.1396x; 1.1396x over previous
#include <cuda_runtime.h>
#include <cuda_bf16.h>
#include <math_constants.h>
#include <cstdint>

// Problem constants
#define BATCH 4
#define SEQ   2048
#define EMBD  1024
#define NHEAD 16
#define HDIM  64
#define QKV3  (3 * EMBD)
#define MTOK  (BATCH * SEQ)   // 8192
#define KD8   (EMBD / 8)      // 128 k-tiles of 8

// ---------------------------------------------------------------------------
// Scratch (__device__ globals) — fragment-major GEMM operands + attn buffers
// A-frag layout [M/16][K/8][lane 32][slot 4] floats
// B-frag layout [N/8][K/8][lane 32][slot 2] floats
// ---------------------------------------------------------------------------
__device__ __align__(16) float    g_xf [(size_t)MTOK * EMBD];     // x (tf32)
__device__ __align__(16) float    g_wfa[(size_t)EMBD * QKV3];     // w_attn^T (tf32)
__device__ __align__(16) float    g_wfp[(size_t)EMBD * EMBD];     // w_proj^T (tf32)
__device__ __align__(16) float    g_af [(size_t)MTOK * EMBD];     // attn out (tf32)
__device__ __align__(16) float    g_q  [(size_t)MTOK * EMBD];     // Q fp32
__device__ __align__(16) uint32_t g_kb [(size_t)MTOK * EMBD / 2]; // K bf16 big
__device__ __align__(16) uint32_t g_ks [(size_t)MTOK * EMBD / 2]; // K bf16 small
__device__ __align__(16) float    g_vt [(size_t)MTOK * EMBD];     // V tf32

// ---------------------------------------------------------------------------
// Helpers
// ---------------------------------------------------------------------------
__device__ __forceinline__ float f2tf(float x) {
    uint32_t u;
    asm("cvt.rna.tf32.f32 %0, %1;" : "=r"(u) : "f"(x));
    return __uint_as_float(u);
}
__device__ __forceinline__ float bfr(float x) {
    return __bfloat162float(__float2bfloat16_rn(x));
}
__device__ __forceinline__ uint32_t pack_bf(float lo, float hi) {
    __nv_bfloat162 h = __floats2bfloat162_rn(lo, hi);
    return *reinterpret_cast<uint32_t*>(&h);
}

__device__ __forceinline__ void mma_tf32(float c[4], const uint32_t a[4],
                                         const uint32_t b[2]) {
    asm volatile(
        "mma.sync.aligned.m16n8k8.row.col.f32.tf32.tf32.f32 "
        "{%0,%1,%2,%3}, {%4,%5,%6,%7}, {%8,%9}, {%0,%1,%2,%3};"
        : "+f"(c[0]), "+f"(c[1]), "+f"(c[2]), "+f"(c[3])
        : "r"(a[0]), "r"(a[1]), "r"(a[2]), "r"(a[3]), "r"(b[0]), "r"(b[1]));
}
__device__ __forceinline__ void mma_bf16(float c[4], const uint32_t a[4],
                                         const uint32_t b[2]) {
    asm volatile(
        "mma.sync.aligned.m16n8k16.row.col.f32.bf16.bf16.f32 "
        "{%0,%1,%2,%3}, {%4,%5,%6,%7}, {%8,%9}, {%0,%1,%2,%3};"
        : "+f"(c[0]), "+f"(c[1]), "+f"(c[2]), "+f"(c[3])
        : "r"(a[0]), "r"(a[1]), "r"(a[2]), "r"(a[3]), "r"(b[0]), "r"(b[1]));
}

__device__ __forceinline__ void cp_async16p(void* dst_smem, const void* src) {
    uint32_t sa = (uint32_t)__cvta_generic_to_shared(dst_smem);
    asm volatile("cp.async.cg.shared.global [%0], [%1], 16;\n"
                 :: "r"(sa), "l"(src));
}
__device__ __forceinline__ void cp_commit() {
    asm volatile("cp.async.commit_group;\n");
}
template<int N>
__device__ __forceinline__ void cp_wait() {
    asm volatile("cp.async.wait_group %0;\n" :: "n"(N));
}

// ---------------------------------------------------------------------------
// Prep kernels: emit fragment-major, tf32-rounded operands.
// Destinations are __device__ symbols referenced in DEVICE code only.
// ---------------------------------------------------------------------------
__global__ __launch_bounds__(256) void prep_a_kernel(
    const float* __restrict__ src)
{
    size_t id = (size_t)blockIdx.x * 256 + threadIdx.x;  // (tile, lane)
    size_t tile = id >> 5;
    int lane = (int)(id & 31);
    int mt = (int)(tile >> 7), kt = (int)(tile & 127);
    int g = lane >> 2, tg = lane & 3;
    const float* s = src + (size_t)(mt * 16 + g) * EMBD + kt * 8 + tg;
    float v0 = s[0];
    float v1 = s[8 * EMBD];
    float v2 = s[4];
    float v3 = s[8 * EMBD + 4];
    *reinterpret_cast<float4*>(g_xf + id * 4) =
        make_float4(f2tf(v0), f2tf(v1), f2tf(v2), f2tf(v3));
}

__device__ __forceinline__ void prep_b_body(
    const float* __restrict__ w, float* __restrict__ dst, int N)
{
    size_t id = (size_t)blockIdx.x * 256 + threadIdx.x;
    size_t tile = id >> 5;
    int lane = (int)(id & 31);
    int nt = (int)(tile >> 7), kt = (int)(tile & 127);
    int g = lane >> 2, tg = lane & 3;
    int n = nt * 8 + g, k = kt * 8 + tg;
    float v0 = w[(size_t)k * N + n];
    float v1 = w[(size_t)(k + 4) * N + n];
    *reinterpret_cast<float2*>(dst + id * 2) = make_float2(f2tf(v0), f2tf(v1));
}

__global__ __launch_bounds__(256) void prep_b_attn_kernel(
    const float* __restrict__ w)
{
    prep_b_body(w, g_wfa, QKV3);
}

__global__ __launch_bounds__(256) void prep_b_proj_kernel(
    const float* __restrict__ w)
{
    prep_b_body(w, g_wfp, EMBD);
}

// ---------------------------------------------------------------------------
// TF32 GEMM, fragment-major operands, BK=32, 3-stage cp.async pipeline.
// (round-9 form exactly — the 734us baseline)
// ---------------------------------------------------------------------------
#define STG_A 4096
#define STG_B 4096
#define STG_FLOATS (STG_A + STG_B)
#define GEMM_SMEM_BYTES (3 * STG_FLOATS * 4)   // 98304

__device__ __forceinline__ void gemm_body(
    const float* __restrict__ Af, const float* __restrict__ Bf,
    const float* __restrict__ bias, float* __restrict__ C, int mode)
{
    extern __shared__ float gsm[];

    const int tid = threadIdx.x, wid = tid >> 5, lane = tid & 31;
    const int g = lane >> 2, tg = lane & 3;
    const int wm = wid & 3, wn = wid >> 2;
    const int row0 = blockIdx.y * 128, col0 = blockIdx.x * 128;
    const int mt0 = blockIdx.y * 8, nt0 = blockIdx.x * 16;

    float c[2][8][4];
#pragma unroll
    for (int mf = 0; mf < 2; mf++)
#pragma unroll
        for (int nf = 0; nf < 8; nf++)
#pragma unroll
            for (int i = 0; i < 4; i++) c[mf][nf][i] = 0.f;

    auto fill = [&](int kb, int st) {
        float* as = gsm + st * STG_FLOATS;
        float* bs = as + STG_A;
#pragma unroll
        for (int l = 0; l < 4; l++) {
            int ch = tid + l * 256;
            int mtl = ch >> 7, off = (ch & 127) * 4;
            cp_async16p(&as[mtl * 512 + off],
                        &Af[((size_t)(mt0 + mtl) * KD8 + kb * 4) * 128 + off]);
        }
#pragma unroll
        for (int l = 0; l < 4; l++) {
            int ch = tid + l * 256;
            int ntl = ch >> 6, off = (ch & 63) * 4;
            cp_async16p(&bs[ntl * 256 + off],
                        &Bf[((size_t)(nt0 + ntl) * KD8 + kb * 4) * 64 + off]);
        }
        cp_commit();
    };

    const int nk = 32;   // K=1024 / BK=32
    fill(0, 0);
    fill(1, 1);

    for (int it = 0; it < nk; it++) {
        if (it + 1 < nk) cp_wait<1>(); else cp_wait<0>();
        __syncthreads();

        const float* as = gsm + (it % 3) * STG_FLOATS;
        const float* bs = as + STG_A;

#pragma unroll
        for (int ktl = 0; ktl < 4; ktl++) {
            uint32_t a[2][4], b[8][2];
#pragma unroll
            for (int mf = 0; mf < 2; mf++) {
                float4 av = *reinterpret_cast<const float4*>(
                    &as[((wm * 2 + mf) * 4 + ktl) * 128 + lane * 4]);
                a[mf][0] = __float_as_uint(av.x);
                a[mf][1] = __float_as_uint(av.y);
                a[mf][2] = __float_as_uint(av.z);
                a[mf][3] = __float_as_uint(av.w);
            }
#pragma unroll
            for (int nf = 0; nf < 8; nf++) {
                float2 bv = *reinterpret_cast<const float2*>(
                    &bs[((wn * 8 + nf) * 4 + ktl) * 64 + lane * 2]);
                b[nf][0] = __float_as_uint(bv.x);
                b[nf][1] = __float_as_uint(bv.y);
            }
#pragma unroll
            for (int mf = 0; mf < 2; mf++)
#pragma unroll
                for (int nf = 0; nf < 8; nf++)
                    mma_tf32(c[mf][nf], a[mf], b[nf]);
        }

        if (it + 2 < nk) fill(it + 2, (it + 2) % 3);
    }

    const int region = col0 >> 10;   // mode 1: 0=Q, 1=K, 2=V

#pragma unroll
    for (int mf = 0; mf < 2; mf++) {
        int r_lo = row0 + wm * 32 + mf * 16 + g;
#pragma unroll
        for (int nf = 0; nf < 8; nf++) {
            int cc = col0 + wn * 64 + nf * 8 + tg * 2;
            float b0 = bias[cc], b1 = bias[cc + 1];
            float v00 = c[mf][nf][0] + b0, v01 = c[mf][nf][1] + b1;
            float v10 = c[mf][nf][2] + b0, v11 = c[mf][nf][3] + b1;
            if (mode == 0) {
                *reinterpret_cast<float2*>(&C[(size_t)r_lo * EMBD + cc]) =
                    make_float2(v00, v01);
                *reinterpret_cast<float2*>(&C[(size_t)(r_lo + 8) * EMBD + cc]) =
                    make_float2(v10, v11);
            } else if (region == 0) {
                *reinterpret_cast<float2*>(&g_q[(size_t)r_lo * EMBD + cc]) =
                    make_float2(v00, v01);
                *reinterpret_cast<float2*>(&g_q[(size_t)(r_lo + 8) * EMBD + cc]) =
                    make_float2(v10, v11);
            } else if (region == 1) {
                int col = cc - EMBD;
                float h00 = bfr(v00), h01 = bfr(v01);
                float h10 = bfr(v10), h11 = bfr(v11);
                size_t w0 = ((size_t)r_lo * EMBD + col) >> 1;
                size_t w1 = ((size_t)(r_lo + 8) * EMBD + col) >> 1;
                g_kb[w0] = pack_bf(h00, h01);
                g_ks[w0] = pack_bf(v00 - h00, v01 - h01);
                g_kb[w1] = pack_bf(h10, h11);
                g_ks[w1] = pack_bf(v10 - h10, v11 - h11);
            } else {
                int col = cc - 2 * EMBD;
                *reinterpret_cast<float2*>(&g_vt[(size_t)r_lo * EMBD + col]) =
                    make_float2(f2tf(v00), f2tf(v01));
                *reinterpret_cast<float2*>(&g_vt[(size_t)(r_lo + 8) * EMBD + col]) =
                    make_float2(f2tf(v10), f2tf(v11));
            }
        }
    }
}

__global__ __launch_bounds__(256, 2) void qkv_gemm_kernel(
    const float* __restrict__ bias)
{
    gemm_body(g_xf, g_wfa, bias, nullptr, 1);
}

__global__ __launch_bounds__(256, 2) void proj_gemm_kernel(
    const float* __restrict__ bias, float* __restrict__ out)
{
    gemm_body(g_af, g_wfp, bias, out, 0);
}

// ---------------------------------------------------------------------------
// Tensor-core flash attention (causal) — round-9 structure with TWO
// subtractive changes:
//  (1) single barrier per tile: sync -> issue kt+1 -> cp_wait -> compute
//      (top barrier proves all kt-1 reads of the reused stage are done)
//  (2) deferred denominator reduction: per-lane partial l, reduced once
//      at the end (row-wide corr factor multiplies all lanes identically)
// ---------------------------------------------------------------------------
#define QKW 36
#define AVS 72
#define APS 68
#define QBW (64 * QKW)
#define STAGE_W (QBW + QBW + 64 * AVS)
#define OFF_ST0 (2 * QBW)
#define OFF_P   (OFF_ST0 + 2 * STAGE_W)
#define ATT_SMEM_BYTES ((OFF_P + 4 * 16 * APS) * 4)   // 109568

__device__ __forceinline__ void st_afrag(float v, int r, int c) {
    size_t idx = ((size_t)(r >> 4) * KD8 + (c >> 3)) * 128
               + ((r & 7) * 4 + (c & 3)) * 4
               + ((r >> 3) & 1) + 2 * ((c >> 2) & 1);
    g_af[idx] = f2tf(v);
}

__global__ __launch_bounds__(128) void flash_attn_kernel()
{
    extern __shared__ uint32_t smw[];
    uint32_t* qb = smw;
    uint32_t* qs = smw + QBW;

    const int tid = threadIdx.x, lane = tid & 31, w = tid >> 5;
    const int g = lane >> 2, tg = lane & 3;
    const int qt = blockIdx.x, h = blockIdx.y, b = blockIdx.z;
    float* ps = reinterpret_cast<float*>(smw + OFF_P) + w * 16 * APS;

    const int bsq = b * SEQ;
    const float scale = 0.125f;

    auto issue_kv = [&](int kt, int st) {
        uint32_t* kbs = smw + OFF_ST0 + st * STAGE_W;
        uint32_t* kss = kbs + QBW;
        float* vss = reinterpret_cast<float*>(kss + QBW);
#pragma unroll
        for (int l = 0; l < 4; l++) {
            int id = tid + l * 128;
            int r = id >> 3, ch = id & 7;
            cp_async16p(&kbs[r * QKW + ch * 4],
                        &g_kb[(size_t)(bsq + kt * 64 + r) * 512 + h * 32 + ch * 4]);
        }
#pragma unroll
        for (int l = 0; l < 4; l++) {
            int id = tid + l * 128;
            int r = id >> 3, ch = id & 7;
            cp_async16p(&kss[r * QKW + ch * 4],
                        &g_ks[(size_t)(bsq + kt * 64 + r) * 512 + h * 32 + ch * 4]);
        }
#pragma unroll
        for (int l = 0; l < 8; l++) {
            int id = tid + l * 128;
            int r = id >> 4, ch = id & 15;
            cp_async16p(&vss[r * AVS + ch * 4],
                        &g_vt[(size_t)(bsq + kt * 64 + r) * EMBD + h * HDIM + ch * 4]);
        }
        cp_commit();
    };

    issue_kv(0, 0);

    // Q tile (scaled, split into bf16 big + small) into smem
#pragma unroll
    for (int l = 0; l < 8; l++) {
        int id = tid + l * 128;
        int r = id >> 4, c = (id & 15) * 4;
        float4 v = *reinterpret_cast<const float4*>(
            &g_q[(size_t)(bsq + qt * 64 + r) * EMBD + h * HDIM + c]);
        v.x *= scale; v.y *= scale; v.z *= scale; v.w *= scale;
        float bx = bfr(v.x), by = bfr(v.y), bz = bfr(v.z), bw = bfr(v.w);
        *reinterpret_cast<uint2*>(&qb[r * QKW + (c >> 1)]) =
            make_uint2(pack_bf(bx, by), pack_bf(bz, bw));
        *reinterpret_cast<uint2*>(&qs[r * QKW + (c >> 1)]) =
            make_uint2(pack_bf(v.x - bx, v.y - by), pack_bf(v.z - bz, v.w - bw));
    }

    float m0 = -CUDART_INF_F, m1 = -CUDART_INF_F;
    float l0 = 0.f, l1 = 0.f;     // PER-LANE partial sums (reduced at end)
    float o[8][4];
#pragma unroll
    for (int nf = 0; nf < 8; nf++)
#pragma unroll
        for (int i = 0; i < 4; i++) o[nf][i] = 0.f;

    const int row_g = qt * 64 + w * 16 + g;
    const int nkt = qt + 1;

    for (int kt = 0; kt < nkt; kt++) {
        // (1) barrier FIRST: all warps done with tile kt-1 (and Q stores on
        // kt==0) -> safe to overwrite stage (kt+1)&1 and to read stage kt&1.
        __syncthreads();
        if (kt + 1 < nkt) { issue_kv(kt + 1, (kt + 1) & 1); cp_wait<1>(); }
        else cp_wait<0>();

        const int st = kt & 1;
        const uint32_t* kbs = smw + OFF_ST0 + st * STAGE_W;
        const uint32_t* kss = kbs + QBW;
        const float* vss = reinterpret_cast<const float*>(kss + QBW);

        float s[8][4];
#pragma unroll
        for (int nf = 0; nf < 8; nf++)
#pragma unroll
            for (int i = 0; i < 4; i++) s[nf][i] = 0.f;

#pragma unroll
        for (int kc = 0; kc < 4; kc++) {
            const int d0w = kc * 8;
            const int r0 = w * 16 + g;
            uint32_t ab[4], as2[4];
            ab[0] = qb[r0 * QKW + d0w + tg];
            ab[1] = qb[(r0 + 8) * QKW + d0w + tg];
            ab[2] = qb[r0 * QKW + d0w + tg + 4];
            ab[3] = qb[(r0 + 8) * QKW + d0w + tg + 4];
            as2[0] = qs[r0 * QKW + d0w + tg];
            as2[1] = qs[(r0 + 8) * QKW + d0w + tg];
            as2[2] = qs[r0 * QKW + d0w + tg + 4];
            as2[3] = qs[(r0 + 8) * QKW + d0w + tg + 4];
#pragma unroll
            for (int nf = 0; nf < 8; nf++) {
                const int t0 = nf * 8;
                uint32_t bb[2], bs[2];
                bb[0] = kbs[(t0 + g) * QKW + d0w + tg];
                bb[1] = kbs[(t0 + g) * QKW + d0w + tg + 4];
                bs[0] = kss[(t0 + g) * QKW + d0w + tg];
                bs[1] = kss[(t0 + g) * QKW + d0w + tg + 4];
                mma_bf16(s[nf], ab, bb);
                mma_bf16(s[nf], as2, bb);
                mma_bf16(s[nf], ab, bs);
            }
        }

        if (kt == qt) {
#pragma unroll
            for (int nf = 0; nf < 8; nf++) {
                int cbase = kt * 64 + nf * 8 + 2 * tg;
                if (cbase > row_g)         s[nf][0] = -CUDART_INF_F;
                if (cbase + 1 > row_g)     s[nf][1] = -CUDART_INF_F;
                if (cbase > row_g + 8)     s[nf][2] = -CUDART_INF_F;
                if (cbase + 1 > row_g + 8) s[nf][3] = -CUDART_INF_F;
            }
        }

        float t0m = -CUDART_INF_F, t1m = -CUDART_INF_F;
#pragma unroll
        for (int nf = 0; nf < 8; nf++) {
            t0m = fmaxf(t0m, fmaxf(s[nf][0], s[nf][1]));
            t1m = fmaxf(t1m, fmaxf(s[nf][2], s[nf][3]));
        }
        t0m = fmaxf(t0m, __shfl_xor_sync(0xffffffffu, t0m, 1));
        t0m = fmaxf(t0m, __shfl_xor_sync(0xffffffffu, t0m, 2));
        t1m = fmaxf(t1m, __shfl_xor_sync(0xffffffffu, t1m, 1));
        t1m = fmaxf(t1m, __shfl_xor_sync(0xffffffffu, t1m, 2));

        float mn0 = fmaxf(m0, t0m), mn1 = fmaxf(m1, t1m);
        float c0 = __expf(m0 - mn0), c1 = __expf(m1 - mn1);

        // (2) per-lane partial psum — NO cross-lane reduction here
        float psum0 = 0.f, psum1 = 0.f;
#pragma unroll
        for (int nf = 0; nf < 8; nf++) {
            float p00 = f2tf(__expf(s[nf][0] - mn0));
            float p01 = f2tf(__expf(s[nf][1] - mn0));
            float p10 = f2tf(__expf(s[nf][2] - mn1));
            float p11 = f2tf(__expf(s[nf][3] - mn1));
            psum0 += p00 + p01;
            psum1 += p10 + p11;
            int cc = nf * 8 + 2 * tg;
            ps[g * APS + cc] = p00;       ps[g * APS + cc + 1] = p01;
            ps[(g + 8) * APS + cc] = p10; ps[(g + 8) * APS + cc + 1] = p11;
        }
        l0 = l0 * c0 + psum0;
        l1 = l1 * c1 + psum1;
        m0 = mn0; m1 = mn1;

#pragma unroll
        for (int nf = 0; nf < 8; nf++) {
            o[nf][0] *= c0; o[nf][1] *= c0;
            o[nf][2] *= c1; o[nf][3] *= c1;
        }

        __syncwarp();   // ps writes visible within warp

        // O += P @ V (tf32, m16n8k8)
#pragma unroll
        for (int kc = 0; kc < 8; kc++) {
            const int t0 = kc * 8;
            uint32_t a[4];
            a[0] = __float_as_uint(ps[g * APS + t0 + tg]);
            a[1] = __float_as_uint(ps[(g + 8) * APS + t0 + tg]);
            a[2] = __float_as_uint(ps[g * APS + t0 + tg + 4]);
            a[3] = __float_as_uint(ps[(g + 8) * APS + t0 + tg + 4]);
#pragma unroll
            for (int nf = 0; nf < 8; nf++) {
                const int d0 = nf * 8;
                uint32_t bv[2];
                bv[0] = __float_as_uint(vss[(t0 + tg) * AVS + d0 + g]);
                bv[1] = __float_as_uint(vss[(t0 + tg + 4) * AVS + d0 + g]);
                mma_tf32(o[nf], a, bv);
            }
        }
        // no trailing sync — the top-of-loop barrier protects stage reuse
    }

    // Final denominator reduction (deferred from the per-tile path)
    l0 += __shfl_xor_sync(0xffffffffu, l0, 1);
    l0 += __shfl_xor_sync(0xffffffffu, l0, 2);
    l1 += __shfl_xor_sync(0xffffffffu, l1, 1);
    l1 += __shfl_xor_sync(0xffffffffu, l1, 2);

    // Epilogue: normalize + write proj A-operand in fragment layout
    float inv0 = 1.f / l0, inv1 = 1.f / l1;
    const int gr0 = bsq + row_g;
#pragma unroll
    for (int nf = 0; nf < 8; nf++) {
        int c0c = h * HDIM + nf * 8 + 2 * tg;
        st_afrag(o[nf][0] * inv0, gr0,     c0c);
        st_afrag(o[nf][1] * inv0, gr0,     c0c + 1);
        st_afrag(o[nf][2] * inv1, gr0 + 8, c0c);
        st_afrag(o[nf][3] * inv1, gr0 + 8, c0c + 1);
    }
}

// ---------------------------------------------------------------------------
// Launch
// ---------------------------------------------------------------------------
extern "C" void kernel_launch(void* const* d_in, const int* in_sizes, int n_in,
                              void* d_out, int out_size)
{
    const float* x      = (const float*)d_in[0];
    const float* w_attn = (const float*)d_in[1];
    const float* b_attn = (const float*)d_in[2];
    const float* w_proj = (const float*)d_in[3];
    const float* b_proj = (const float*)d_in[4];
    float* out = (float*)d_out;

    cudaFuncSetAttribute(qkv_gemm_kernel,
                         cudaFuncAttributeMaxDynamicSharedMemorySize,
                         GEMM_SMEM_BYTES);
    cudaFuncSetAttribute(proj_gemm_kernel,
                         cudaFuncAttributeMaxDynamicSharedMemorySize,
                         GEMM_SMEM_BYTES);
    cudaFuncSetAttribute(flash_attn_kernel,
                         cudaFuncAttributeMaxDynamicSharedMemorySize,
                         ATT_SMEM_BYTES);

    // Prep: x -> A-frag, W^T -> B-frag (tf32-rounded once)
    prep_a_kernel<<<(unsigned)(((size_t)(MTOK / 16) * KD8 * 32) / 256), 256>>>(x);
    prep_b_attn_kernel<<<(unsigned)(((size_t)(QKV3 / 8) * KD8 * 32) / 256), 256>>>(
        w_attn);
    prep_b_proj_kernel<<<(unsigned)(((size_t)(EMBD / 8) * KD8 * 32) / 256), 256>>>(
        w_proj);

    // QKV GEMM -> Q/K/V attention buffers
    qkv_gemm_kernel<<<dim3(QKV3 / 128, MTOK / 128), 256, GEMM_SMEM_BYTES>>>(
        b_attn);

    // Flash attention -> proj A-operand (frag layout)
    flash_attn_kernel<<<dim3(SEQ / 64, NHEAD, BATCH), 128, ATT_SMEM_BYTES>>>();

    // Proj GEMM -> out
    proj_gemm_kernel<<<dim3(EMBD / 128, MTOK / 128), 256, GEMM_SMEM_BYTES>>>(
        b_proj, out);
}

// round 17
// speedup vs baseline: 1.1765x; 1.0324x over previous
#include <cuda_runtime.h>
#include <cuda_bf16.h>
#include <math_constants.h>
#include <cstdint>

// Problem constants
#define BATCH 4
#define SEQ   2048
#define EMBD  1024
#define NHEAD 16
#define HDIM  64
#define QKV3  (3 * EMBD)
#define MTOK  (BATCH * SEQ)   // 8192
#define KD8   (EMBD / 8)      // 128 k-tiles of 8

// ---------------------------------------------------------------------------
// Scratch (__device__ globals) — fragment-major GEMM operands + attn buffers
// A-frag layout [M/16][K/8][lane 32][slot 4] floats
// B-frag layout [N/8][K/8][lane 32][slot 2] floats
// ---------------------------------------------------------------------------
__device__ __align__(16) float    g_xf [(size_t)MTOK * EMBD];     // x (tf32)
__device__ __align__(16) float    g_wfa[(size_t)EMBD * QKV3];     // w_attn^T (tf32)
__device__ __align__(16) float    g_wfp[(size_t)EMBD * EMBD];     // w_proj^T (tf32)
__device__ __align__(16) float    g_af [(size_t)MTOK * EMBD];     // attn out (tf32)
__device__ __align__(16) float    g_q  [(size_t)MTOK * EMBD];     // Q fp32
__device__ __align__(16) uint32_t g_kb [(size_t)MTOK * EMBD / 2]; // K bf16 big
__device__ __align__(16) uint32_t g_ks [(size_t)MTOK * EMBD / 2]; // K bf16 small
__device__ __align__(16) float    g_vt [(size_t)MTOK * EMBD];     // V tf32

// ---------------------------------------------------------------------------
// Helpers
// ---------------------------------------------------------------------------
__device__ __forceinline__ float f2tf(float x) {
    uint32_t u;
    asm("cvt.rna.tf32.f32 %0, %1;" : "=r"(u) : "f"(x));
    return __uint_as_float(u);
}
__device__ __forceinline__ float bfr(float x) {
    return __bfloat162float(__float2bfloat16_rn(x));
}
__device__ __forceinline__ uint32_t pack_bf(float lo, float hi) {
    __nv_bfloat162 h = __floats2bfloat162_rn(lo, hi);
    return *reinterpret_cast<uint32_t*>(&h);
}

__device__ __forceinline__ void mma_tf32(float c[4], const uint32_t a[4],
                                         const uint32_t b[2]) {
    asm volatile(
        "mma.sync.aligned.m16n8k8.row.col.f32.tf32.tf32.f32 "
        "{%0,%1,%2,%3}, {%4,%5,%6,%7}, {%8,%9}, {%0,%1,%2,%3};"
        : "+f"(c[0]), "+f"(c[1]), "+f"(c[2]), "+f"(c[3])
        : "r"(a[0]), "r"(a[1]), "r"(a[2]), "r"(a[3]), "r"(b[0]), "r"(b[1]));
}
__device__ __forceinline__ void mma_bf16(float c[4], const uint32_t a[4],
                                         const uint32_t b[2]) {
    asm volatile(
        "mma.sync.aligned.m16n8k16.row.col.f32.bf16.bf16.f32 "
        "{%0,%1,%2,%3}, {%4,%5,%6,%7}, {%8,%9}, {%0,%1,%2,%3};"
        : "+f"(c[0]), "+f"(c[1]), "+f"(c[2]), "+f"(c[3])
        : "r"(a[0]), "r"(a[1]), "r"(a[2]), "r"(a[3]), "r"(b[0]), "r"(b[1]));
}

__device__ __forceinline__ void cp_async16p(void* dst_smem, const void* src) {
    uint32_t sa = (uint32_t)__cvta_generic_to_shared(dst_smem);
    asm volatile("cp.async.cg.shared.global [%0], [%1], 16;\n"
                 :: "r"(sa), "l"(src));
}
__device__ __forceinline__ void cp_commit() {
    asm volatile("cp.async.commit_group;\n");
}
template<int N>
__device__ __forceinline__ void cp_wait() {
    asm volatile("cp.async.wait_group %0;\n" :: "n"(N));
}

// ---------------------------------------------------------------------------
// Fused prep kernel: one launch covers x -> A-frag and both W^T -> B-frag.
// Region boundaries are exact block multiples, so every block is uniform.
// ---------------------------------------------------------------------------
#define PREP_A_THREADS  ((size_t)(MTOK / 16) * KD8 * 32)    // 2097152
#define PREP_BA_THREADS ((size_t)(QKV3 / 8) * KD8 * 32)     // 1572864
#define PREP_BP_THREADS ((size_t)(EMBD / 8) * KD8 * 32)     // 524288
#define PREP_TOTAL_BLOCKS \
    (unsigned)((PREP_A_THREADS + PREP_BA_THREADS + PREP_BP_THREADS) / 256)

__device__ __forceinline__ void prep_a_body(
    const float* __restrict__ src, size_t id)
{
    size_t tile = id >> 5;
    int lane = (int)(id & 31);
    int mt = (int)(tile >> 7), kt = (int)(tile & 127);
    int g = lane >> 2, tg = lane & 3;
    const float* s = src + (size_t)(mt * 16 + g) * EMBD + kt * 8 + tg;
    float v0 = s[0];
    float v1 = s[8 * EMBD];
    float v2 = s[4];
    float v3 = s[8 * EMBD + 4];
    *reinterpret_cast<float4*>(g_xf + id * 4) =
        make_float4(f2tf(v0), f2tf(v1), f2tf(v2), f2tf(v3));
}

__device__ __forceinline__ void prep_b_body(
    const float* __restrict__ w, float* __restrict__ dst, int N, size_t id)
{
    size_t tile = id >> 5;
    int lane = (int)(id & 31);
    int nt = (int)(tile >> 7), kt = (int)(tile & 127);
    int g = lane >> 2, tg = lane & 3;
    int n = nt * 8 + g, k = kt * 8 + tg;
    float v0 = w[(size_t)k * N + n];
    float v1 = w[(size_t)(k + 4) * N + n];
    *reinterpret_cast<float2*>(dst + id * 2) = make_float2(f2tf(v0), f2tf(v1));
}

__global__ __launch_bounds__(256) void prep_all_kernel(
    const float* __restrict__ x, const float* __restrict__ wa,
    const float* __restrict__ wp)
{
    size_t id = (size_t)blockIdx.x * 256 + threadIdx.x;
    if (id < PREP_A_THREADS) {
        prep_a_body(x, id);
    } else if (id < PREP_A_THREADS + PREP_BA_THREADS) {
        prep_b_body(wa, g_wfa, QKV3, id - PREP_A_THREADS);
    } else {
        prep_b_body(wp, g_wfp, EMBD, id - PREP_A_THREADS - PREP_BA_THREADS);
    }
}

// ---------------------------------------------------------------------------
// TF32 GEMM, fragment-major operands, BK=32, 3-stage cp.async pipeline.
// (round-9/16 form exactly)
// ---------------------------------------------------------------------------
#define STG_A 4096
#define STG_B 4096
#define STG_FLOATS (STG_A + STG_B)
#define GEMM_SMEM_BYTES (3 * STG_FLOATS * 4)   // 98304

__device__ __forceinline__ void gemm_body(
    const float* __restrict__ Af, const float* __restrict__ Bf,
    const float* __restrict__ bias, float* __restrict__ C, int mode)
{
    extern __shared__ float gsm[];

    const int tid = threadIdx.x, wid = tid >> 5, lane = tid & 31;
    const int g = lane >> 2, tg = lane & 3;
    const int wm = wid & 3, wn = wid >> 2;
    const int row0 = blockIdx.y * 128, col0 = blockIdx.x * 128;
    const int mt0 = blockIdx.y * 8, nt0 = blockIdx.x * 16;

    float c[2][8][4];
#pragma unroll
    for (int mf = 0; mf < 2; mf++)
#pragma unroll
        for (int nf = 0; nf < 8; nf++)
#pragma unroll
            for (int i = 0; i < 4; i++) c[mf][nf][i] = 0.f;

    auto fill = [&](int kb, int st) {
        float* as = gsm + st * STG_FLOATS;
        float* bs = as + STG_A;
#pragma unroll
        for (int l = 0; l < 4; l++) {
            int ch = tid + l * 256;
            int mtl = ch >> 7, off = (ch & 127) * 4;
            cp_async16p(&as[mtl * 512 + off],
                        &Af[((size_t)(mt0 + mtl) * KD8 + kb * 4) * 128 + off]);
        }
#pragma unroll
        for (int l = 0; l < 4; l++) {
            int ch = tid + l * 256;
            int ntl = ch >> 6, off = (ch & 63) * 4;
            cp_async16p(&bs[ntl * 256 + off],
                        &Bf[((size_t)(nt0 + ntl) * KD8 + kb * 4) * 64 + off]);
        }
        cp_commit();
    };

    const int nk = 32;   // K=1024 / BK=32
    fill(0, 0);
    fill(1, 1);

    for (int it = 0; it < nk; it++) {
        if (it + 1 < nk) cp_wait<1>(); else cp_wait<0>();
        __syncthreads();

        const float* as = gsm + (it % 3) * STG_FLOATS;
        const float* bs = as + STG_A;

#pragma unroll
        for (int ktl = 0; ktl < 4; ktl++) {
            uint32_t a[2][4], b[8][2];
#pragma unroll
            for (int mf = 0; mf < 2; mf++) {
                float4 av = *reinterpret_cast<const float4*>(
                    &as[((wm * 2 + mf) * 4 + ktl) * 128 + lane * 4]);
                a[mf][0] = __float_as_uint(av.x);
                a[mf][1] = __float_as_uint(av.y);
                a[mf][2] = __float_as_uint(av.z);
                a[mf][3] = __float_as_uint(av.w);
            }
#pragma unroll
            for (int nf = 0; nf < 8; nf++) {
                float2 bv = *reinterpret_cast<const float2*>(
                    &bs[((wn * 8 + nf) * 4 + ktl) * 64 + lane * 2]);
                b[nf][0] = __float_as_uint(bv.x);
                b[nf][1] = __float_as_uint(bv.y);
            }
#pragma unroll
            for (int mf = 0; mf < 2; mf++)
#pragma unroll
                for (int nf = 0; nf < 8; nf++)
                    mma_tf32(c[mf][nf], a[mf], b[nf]);
        }

        if (it + 2 < nk) fill(it + 2, (it + 2) % 3);
    }

    const int region = col0 >> 10;   // mode 1: 0=Q, 1=K, 2=V

#pragma unroll
    for (int mf = 0; mf < 2; mf++) {
        int r_lo = row0 + wm * 32 + mf * 16 + g;
#pragma unroll
        for (int nf = 0; nf < 8; nf++) {
            int cc = col0 + wn * 64 + nf * 8 + tg * 2;
            float b0 = bias[cc], b1 = bias[cc + 1];
            float v00 = c[mf][nf][0] + b0, v01 = c[mf][nf][1] + b1;
            float v10 = c[mf][nf][2] + b0, v11 = c[mf][nf][3] + b1;
            if (mode == 0) {
                *reinterpret_cast<float2*>(&C[(size_t)r_lo * EMBD + cc]) =
                    make_float2(v00, v01);
                *reinterpret_cast<float2*>(&C[(size_t)(r_lo + 8) * EMBD + cc]) =
                    make_float2(v10, v11);
            } else if (region == 0) {
                *reinterpret_cast<float2*>(&g_q[(size_t)r_lo * EMBD + cc]) =
                    make_float2(v00, v01);
                *reinterpret_cast<float2*>(&g_q[(size_t)(r_lo + 8) * EMBD + cc]) =
                    make_float2(v10, v11);
            } else if (region == 1) {
                int col = cc - EMBD;
                float h00 = bfr(v00), h01 = bfr(v01);
                float h10 = bfr(v10), h11 = bfr(v11);
                size_t w0 = ((size_t)r_lo * EMBD + col) >> 1;
                size_t w1 = ((size_t)(r_lo + 8) * EMBD + col) >> 1;
                g_kb[w0] = pack_bf(h00, h01);
                g_ks[w0] = pack_bf(v00 - h00, v01 - h01);
                g_kb[w1] = pack_bf(h10, h11);
                g_ks[w1] = pack_bf(v10 - h10, v11 - h11);
            } else {
                int col = cc - 2 * EMBD;
                *reinterpret_cast<float2*>(&g_vt[(size_t)r_lo * EMBD + col]) =
                    make_float2(f2tf(v00), f2tf(v01));
                *reinterpret_cast<float2*>(&g_vt[(size_t)(r_lo + 8) * EMBD + col]) =
                    make_float2(f2tf(v10), f2tf(v11));
            }
        }
    }
}

__global__ __launch_bounds__(256, 2) void qkv_gemm_kernel(
    const float* __restrict__ bias)
{
    gemm_body(g_xf, g_wfa, bias, nullptr, 1);
}

__global__ __launch_bounds__(256, 2) void proj_gemm_kernel(
    const float* __restrict__ bias, float* __restrict__ out)
{
    gemm_body(g_af, g_wfp, bias, out, 0);
}

// ---------------------------------------------------------------------------
// Tensor-core flash attention (causal) — round-16 inner loop, with qt
// REVERSED: heavy diagonal blocks launch first for better tail packing.
// ---------------------------------------------------------------------------
#define QKW 36
#define AVS 72
#define APS 68
#define QBW (64 * QKW)
#define STAGE_W (QBW + QBW + 64 * AVS)
#define OFF_ST0 (2 * QBW)
#define OFF_P   (OFF_ST0 + 2 * STAGE_W)
#define ATT_SMEM_BYTES ((OFF_P + 4 * 16 * APS) * 4)   // 109568

__device__ __forceinline__ void st_afrag(float v, int r, int c) {
    size_t idx = ((size_t)(r >> 4) * KD8 + (c >> 3)) * 128
               + ((r & 7) * 4 + (c & 3)) * 4
               + ((r >> 3) & 1) + 2 * ((c >> 2) & 1);
    g_af[idx] = f2tf(v);
}

__global__ __launch_bounds__(128) void flash_attn_kernel()
{
    extern __shared__ uint32_t smw[];
    uint32_t* qb = smw;
    uint32_t* qs = smw + QBW;

    const int tid = threadIdx.x, lane = tid & 31, w = tid >> 5;
    const int g = lane >> 2, tg = lane & 3;
    const int qt = (SEQ / 64) - 1 - blockIdx.x;   // REVERSED: heavy first
    const int h = blockIdx.y, b = blockIdx.z;
    float* ps = reinterpret_cast<float*>(smw + OFF_P) + w * 16 * APS;

    const int bsq = b * SEQ;
    const float scale = 0.125f;

    auto issue_kv = [&](int kt, int st) {
        uint32_t* kbs = smw + OFF_ST0 + st * STAGE_W;
        uint32_t* kss = kbs + QBW;
        float* vss = reinterpret_cast<float*>(kss + QBW);
#pragma unroll
        for (int l = 0; l < 4; l++) {
            int id = tid + l * 128;
            int r = id >> 3, ch = id & 7;
            cp_async16p(&kbs[r * QKW + ch * 4],
                        &g_kb[(size_t)(bsq + kt * 64 + r) * 512 + h * 32 + ch * 4]);
        }
#pragma unroll
        for (int l = 0; l < 4; l++) {
            int id = tid + l * 128;
            int r = id >> 3, ch = id & 7;
            cp_async16p(&kss[r * QKW + ch * 4],
                        &g_ks[(size_t)(bsq + kt * 64 + r) * 512 + h * 32 + ch * 4]);
        }
#pragma unroll
        for (int l = 0; l < 8; l++) {
            int id = tid + l * 128;
            int r = id >> 4, ch = id & 15;
            cp_async16p(&vss[r * AVS + ch * 4],
                        &g_vt[(size_t)(bsq + kt * 64 + r) * EMBD + h * HDIM + ch * 4]);
        }
        cp_commit();
    };

    issue_kv(0, 0);

    // Q tile (scaled, split into bf16 big + small) into smem
#pragma unroll
    for (int l = 0; l < 8; l++) {
        int id = tid + l * 128;
        int r = id >> 4, c = (id & 15) * 4;
        float4 v = *reinterpret_cast<const float4*>(
            &g_q[(size_t)(bsq + qt * 64 + r) * EMBD + h * HDIM + c]);
        v.x *= scale; v.y *= scale; v.z *= scale; v.w *= scale;
        float bx = bfr(v.x), by = bfr(v.y), bz = bfr(v.z), bw = bfr(v.w);
        *reinterpret_cast<uint2*>(&qb[r * QKW + (c >> 1)]) =
            make_uint2(pack_bf(bx, by), pack_bf(bz, bw));
        *reinterpret_cast<uint2*>(&qs[r * QKW + (c >> 1)]) =
            make_uint2(pack_bf(v.x - bx, v.y - by), pack_bf(v.z - bz, v.w - bw));
    }

    float m0 = -CUDART_INF_F, m1 = -CUDART_INF_F;
    float l0 = 0.f, l1 = 0.f;     // per-lane partial sums (reduced at end)
    float o[8][4];
#pragma unroll
    for (int nf = 0; nf < 8; nf++)
#pragma unroll
        for (int i = 0; i < 4; i++) o[nf][i] = 0.f;

    const int row_g = qt * 64 + w * 16 + g;
    const int nkt = qt + 1;

    for (int kt = 0; kt < nkt; kt++) {
        // barrier FIRST: all warps done with tile kt-1 (and Q stores on
        // kt==0) -> safe to overwrite stage (kt+1)&1 and to read stage kt&1.
        __syncthreads();
        if (kt + 1 < nkt) { issue_kv(kt + 1, (kt + 1) & 1); cp_wait<1>(); }
        else cp_wait<0>();

        const int st = kt & 1;
        const uint32_t* kbs = smw + OFF_ST0 + st * STAGE_W;
        const uint32_t* kss = kbs + QBW;
        const float* vss = reinterpret_cast<const float*>(kss + QBW);

        float s[8][4];
#pragma unroll
        for (int nf = 0; nf < 8; nf++)
#pragma unroll
            for (int i = 0; i < 4; i++) s[nf][i] = 0.f;

#pragma unroll
        for (int kc = 0; kc < 4; kc++) {
            const int d0w = kc * 8;
            const int r0 = w * 16 + g;
            uint32_t ab[4], as2[4];
            ab[0] = qb[r0 * QKW + d0w + tg];
            ab[1] = qb[(r0 + 8) * QKW + d0w + tg];
            ab[2] = qb[r0 * QKW + d0w + tg + 4];
            ab[3] = qb[(r0 + 8) * QKW + d0w + tg + 4];
            as2[0] = qs[r0 * QKW + d0w + tg];
            as2[1] = qs[(r0 + 8) * QKW + d0w + tg];
            as2[2] = qs[r0 * QKW + d0w + tg + 4];
            as2[3] = qs[(r0 + 8) * QKW + d0w + tg + 4];
#pragma unroll
            for (int nf = 0; nf < 8; nf++) {
                const int t0 = nf * 8;
                uint32_t bb[2], bs[2];
                bb[0] = kbs[(t0 + g) * QKW + d0w + tg];
                bb[1] = kbs[(t0 + g) * QKW + d0w + tg + 4];
                bs[0] = kss[(t0 + g) * QKW + d0w + tg];
                bs[1] = kss[(t0 + g) * QKW + d0w + tg + 4];
                mma_bf16(s[nf], ab, bb);
                mma_bf16(s[nf], as2, bb);
                mma_bf16(s[nf], ab, bs);
            }
        }

        if (kt == qt) {
#pragma unroll
            for (int nf = 0; nf < 8; nf++) {
                int cbase = kt * 64 + nf * 8 + 2 * tg;
                if (cbase > row_g)         s[nf][0] = -CUDART_INF_F;
                if (cbase + 1 > row_g)     s[nf][1] = -CUDART_INF_F;
                if (cbase > row_g + 8)     s[nf][2] = -CUDART_INF_F;
                if (cbase + 1 > row_g + 8) s[nf][3] = -CUDART_INF_F;
            }
        }

        float t0m = -CUDART_INF_F, t1m = -CUDART_INF_F;
#pragma unroll
        for (int nf = 0; nf < 8; nf++) {
            t0m = fmaxf(t0m, fmaxf(s[nf][0], s[nf][1]));
            t1m = fmaxf(t1m, fmaxf(s[nf][2], s[nf][3]));
        }
        t0m = fmaxf(t0m, __shfl_xor_sync(0xffffffffu, t0m, 1));
        t0m = fmaxf(t0m, __shfl_xor_sync(0xffffffffu, t0m, 2));
        t1m = fmaxf(t1m, __shfl_xor_sync(0xffffffffu, t1m, 1));
        t1m = fmaxf(t1m, __shfl_xor_sync(0xffffffffu, t1m, 2));

        float mn0 = fmaxf(m0, t0m), mn1 = fmaxf(m1, t1m);
        float c0 = __expf(m0 - mn0), c1 = __expf(m1 - mn1);

        // per-lane partial psum — no cross-lane reduction here
        float psum0 = 0.f, psum1 = 0.f;
#pragma unroll
        for (int nf = 0; nf < 8; nf++) {
            float p00 = f2tf(__expf(s[nf][0] - mn0));
            float p01 = f2tf(__expf(s[nf][1] - mn0));
            float p10 = f2tf(__expf(s[nf][2] - mn1));
            float p11 = f2tf(__expf(s[nf][3] - mn1));
            psum0 += p00 + p01;
            psum1 += p10 + p11;
            int cc = nf * 8 + 2 * tg;
            ps[g * APS + cc] = p00;       ps[g * APS + cc + 1] = p01;
            ps[(g + 8) * APS + cc] = p10; ps[(g + 8) * APS + cc + 1] = p11;
        }
        l0 = l0 * c0 + psum0;
        l1 = l1 * c1 + psum1;
        m0 = mn0; m1 = mn1;

#pragma unroll
        for (int nf = 0; nf < 8; nf++) {
            o[nf][0] *= c0; o[nf][1] *= c0;
            o[nf][2] *= c1; o[nf][3] *= c1;
        }

        __syncwarp();   // ps writes visible within warp

        // O += P @ V (tf32, m16n8k8)
#pragma unroll
        for (int kc = 0; kc < 8; kc++) {
            const int t0 = kc * 8;
            uint32_t a[4];
            a[0] = __float_as_uint(ps[g * APS + t0 + tg]);
            a[1] = __float_as_uint(ps[(g + 8) * APS + t0 + tg]);
            a[2] = __float_as_uint(ps[g * APS + t0 + tg + 4]);
            a[3] = __float_as_uint(ps[(g + 8) * APS + t0 + tg + 4]);
#pragma unroll
            for (int nf = 0; nf < 8; nf++) {
                const int d0 = nf * 8;
                uint32_t bv[2];
                bv[0] = __float_as_uint(vss[(t0 + tg) * AVS + d0 + g]);
                bv[1] = __float_as_uint(vss[(t0 + tg + 4) * AVS + d0 + g]);
                mma_tf32(o[nf], a, bv);
            }
        }
        // no trailing sync — the top-of-loop barrier protects stage reuse
    }

    // Final denominator reduction (deferred from the per-tile path)
    l0 += __shfl_xor_sync(0xffffffffu, l0, 1);
    l0 += __shfl_xor_sync(0xffffffffu, l0, 2);
    l1 += __shfl_xor_sync(0xffffffffu, l1, 1);
    l1 += __shfl_xor_sync(0xffffffffu, l1, 2);

    // Epilogue: normalize + write proj A-operand in fragment layout
    float inv0 = 1.f / l0, inv1 = 1.f / l1;
    const int gr0 = bsq + row_g;
#pragma unroll
    for (int nf = 0; nf < 8; nf++) {
        int c0c = h * HDIM + nf * 8 + 2 * tg;
        st_afrag(o[nf][0] * inv0, gr0,     c0c);
        st_afrag(o[nf][1] * inv0, gr0,     c0c + 1);
        st_afrag(o[nf][2] * inv1, gr0 + 8, c0c);
        st_afrag(o[nf][3] * inv1, gr0 + 8, c0c + 1);
    }
}

// ---------------------------------------------------------------------------
// Launch
// ---------------------------------------------------------------------------
extern "C" void kernel_launch(void* const* d_in, const int* in_sizes, int n_in,
                              void* d_out, int out_size)
{
    const float* x      = (const float*)d_in[0];
    const float* w_attn = (const float*)d_in[1];
    const float* b_attn = (const float*)d_in[2];
    const float* w_proj = (const float*)d_in[3];
    const float* b_proj = (const float*)d_in[4];
    float* out = (float*)d_out;

    cudaFuncSetAttribute(qkv_gemm_kernel,
                         cudaFuncAttributeMaxDynamicSharedMemorySize,
                         GEMM_SMEM_BYTES);
    cudaFuncSetAttribute(proj_gemm_kernel,
                         cudaFuncAttributeMaxDynamicSharedMemorySize,
                         GEMM_SMEM_BYTES);
    cudaFuncSetAttribute(flash_attn_kernel,
                         cudaFuncAttributeMaxDynamicSharedMemorySize,
                         ATT_SMEM_BYTES);

    // Fused prep: x -> A-frag, both W^T -> B-frag (tf32-rounded once)
    prep_all_kernel<<<PREP_TOTAL_BLOCKS, 256>>>(x, w_attn, w_proj);

    // QKV GEMM -> Q/K/V attention buffers
    qkv_gemm_kernel<<<dim3(QKV3 / 128, MTOK / 128), 256, GEMM_SMEM_BYTES>>>(
        b_attn);

    // Flash attention (heavy blocks first) -> proj A-operand (frag layout)
    flash_attn_kernel<<<dim3(SEQ / 64, NHEAD, BATCH), 128, ATT_SMEM_BYTES>>>();

    // Proj GEMM -> out
    proj_gemm_kernel<<<dim3(EMBD / 128, MTOK / 128), 256, GEMM_SMEM_BYTES>>>(
        b_proj, out);
}